// round 2
// baseline (speedup 1.0000x reference)
#include <cuda_runtime.h>
#include <math.h>

#define B 2
#define S 2048
#define D 2048
#define NH 16
#define HD 128
#define M_ROWS (B * S)

// Scratch (allocation-free rule: __device__ globals)
__device__ float g_q[(size_t)M_ROWS * D];
__device__ float g_k[(size_t)M_ROWS * D];
__device__ float g_v[(size_t)M_ROWS * D];
__device__ float g_o[(size_t)M_ROWS * D];

// ---------------------------------------------------------------------------
// C[M,N] = A[M,K] @ W[N,K]^T + bias[N]   (both operands K-contiguous)
// 128x128 block tile, BK=8, 256 threads, 8x8 per thread.
// Global loads for slab k0+8 are prefetched into registers during compute
// of slab k0 (hides DRAM/L2 latency).
// ---------------------------------------------------------------------------
__global__ __launch_bounds__(256) void gemm_nt_bias(
    const float* __restrict__ A, const float* __restrict__ Wt,
    const float* __restrict__ bias, float* __restrict__ C,
    int K, int N)
{
    __shared__ float As[8][128];
    __shared__ float Bs[8][128];
    const int bm = blockIdx.y * 128;
    const int bn = blockIdx.x * 128;
    const int tid = threadIdx.x;
    const int tx = tid & 15;      // 0..15
    const int ty = tid >> 4;      // 0..15
    const int lr  = tid >> 1;     // 0..127 tile row for loads
    const int lc4 = (tid & 1) * 4; // 0 or 4

    const float* Ap = A  + (size_t)(bm + lr) * K + lc4;
    const float* Wp = Wt + (size_t)(bn + lr) * K + lc4;

    float acc[8][8];
#pragma unroll
    for (int i = 0; i < 8; ++i)
#pragma unroll
        for (int j = 0; j < 8; ++j) acc[i][j] = 0.f;

    float4 av = *(const float4*)(Ap);
    float4 wv = *(const float4*)(Wp);

    for (int k0 = 0; k0 < K; k0 += 8) {
        As[lc4 + 0][lr] = av.x; As[lc4 + 1][lr] = av.y;
        As[lc4 + 2][lr] = av.z; As[lc4 + 3][lr] = av.w;
        Bs[lc4 + 0][lr] = wv.x; Bs[lc4 + 1][lr] = wv.y;
        Bs[lc4 + 2][lr] = wv.z; Bs[lc4 + 3][lr] = wv.w;
        __syncthreads();
        if (k0 + 8 < K) {
            av = *(const float4*)(Ap + k0 + 8);
            wv = *(const float4*)(Wp + k0 + 8);
        }
#pragma unroll
        for (int kk = 0; kk < 8; ++kk) {
            float a[8], b[8];
            *(float4*)&a[0] = *(const float4*)&As[kk][ty * 8];
            *(float4*)&a[4] = *(const float4*)&As[kk][ty * 8 + 4];
            *(float4*)&b[0] = *(const float4*)&Bs[kk][tx * 8];
            *(float4*)&b[4] = *(const float4*)&Bs[kk][tx * 8 + 4];
#pragma unroll
            for (int i = 0; i < 8; ++i)
#pragma unroll
                for (int j = 0; j < 8; ++j)
                    acc[i][j] += a[i] * b[j];
        }
        __syncthreads();
    }

#pragma unroll
    for (int i = 0; i < 8; ++i) {
        float* Cp = C + (size_t)(bm + ty * 8 + i) * N + bn + tx * 8;
        const float* bp = bias + bn + tx * 8;
#pragma unroll
        for (int j = 0; j < 8; j += 4) {
            float4 v;
            v.x = acc[i][j + 0] + bp[j + 0];
            v.y = acc[i][j + 1] + bp[j + 1];
            v.z = acc[i][j + 2] + bp[j + 2];
            v.w = acc[i][j + 3] + bp[j + 3];
            *(float4*)(Cp + j) = v;
        }
    }
}

// ---------------------------------------------------------------------------
// Fused RMSNorm (over full D) * g, then RoPE per head. In-place.
// One block per token row; thread t owns floats [8t, 8t+8) = 4 rope pairs.
// ---------------------------------------------------------------------------
__global__ __launch_bounds__(256) void rmsnorm_rope(
    float* __restrict__ t, const float* __restrict__ g,
    const float* __restrict__ freqs)
{
    const int row = blockIdx.x;
    const int s = row & (S - 1);
    const int tid = threadIdx.x;
    float* p = t + (size_t)row * D;

    float4 v0 = *(const float4*)(p + tid * 8);
    float4 v1 = *(const float4*)(p + tid * 8 + 4);
    float ss = v0.x * v0.x + v0.y * v0.y + v0.z * v0.z + v0.w * v0.w
             + v1.x * v1.x + v1.y * v1.y + v1.z * v1.z + v1.w * v1.w;

    __shared__ float red[256];
    red[tid] = ss;
    __syncthreads();
    for (int off = 128; off > 0; off >>= 1) {
        if (tid < off) red[tid] += red[tid + off];
        __syncthreads();
    }
    const float inv = rsqrtf(red[0] / (float)D + 1e-6f);

    float4 g0 = *(const float4*)(g + tid * 8);
    float4 g1 = *(const float4*)(g + tid * 8 + 4);
    float u[8];
    u[0] = v0.x * inv * g0.x; u[1] = v0.y * inv * g0.y;
    u[2] = v0.z * inv * g0.z; u[3] = v0.w * inv * g0.w;
    u[4] = v1.x * inv * g1.x; u[5] = v1.y * inv * g1.y;
    u[6] = v1.z * inv * g1.z; u[7] = v1.w * inv * g1.w;

    float r[8];
#pragma unroll
    for (int j = 0; j < 4; ++j) {
        int pidx = tid * 4 + j;       // global pair index within row
        int i = pidx & 63;            // pair index within head (HD/2 = 64)
        float sn, cs;
        sincosf(freqs[(size_t)s * 64 + i], &sn, &cs);
        float re = u[2 * j], im = u[2 * j + 1];
        r[2 * j]     = re * cs - im * sn;
        r[2 * j + 1] = re * sn + im * cs;
    }
    float4 w0 = make_float4(r[0], r[1], r[2], r[3]);
    float4 w1 = make_float4(r[4], r[5], r[6], r[7]);
    *(float4*)(p + tid * 8) = w0;
    *(float4*)(p + tid * 8 + 4) = w1;
}

// ---------------------------------------------------------------------------
// Flash attention: one block per (b, head, 64-query tile). Online softmax.
// smem: sQ^T[128][64] (prescaled), sK^T[128][64], sV[64][128], sS[64][64].
// ---------------------------------------------------------------------------
#define ATTN_SMEM_FLOATS (128 * 64 + 128 * 64 + 64 * 128 + 64 * 64 + 3 * 64)
#define ATTN_SMEM_BYTES (ATTN_SMEM_FLOATS * 4)

__global__ __launch_bounds__(256) void flash_attn(
    const float* __restrict__ Qg, const float* __restrict__ Kg,
    const float* __restrict__ Vg, const int* __restrict__ seq_lens,
    float* __restrict__ Og)
{
    extern __shared__ float sm[];
    float* sQ  = sm;                  // [128][64]  (k-major)
    float* sK  = sQ + 128 * 64;       // [128][64]  (k-major)
    float* sV  = sK + 128 * 64;       // [64][128]
    float* sS  = sV + 64 * 128;       // [64][64]
    float* sMx = sS + 64 * 64;        // [64]
    float* sL  = sMx + 64;            // [64]
    float* sAl = sL + 64;             // [64]

    const int tid = threadIdx.x;
    const int bh = blockIdx.y;
    const int b = bh >> 4;
    const int h = bh & 15;
    const int q0 = blockIdx.x * 64;
    const int len = seq_lens[b];
    const float scale = 0.088388347648318447f;  // 1/sqrt(128)

    const float* Qb = Qg + (size_t)b * S * D + h * HD;
    const float* Kb = Kg + (size_t)b * S * D + h * HD;
    const float* Vb = Vg + (size_t)b * S * D + h * HD;

    // Load Q tile transposed, pre-scaled
    for (int idx = tid; idx < 64 * 32; idx += 256) {
        int q = idx >> 5;
        int k4 = (idx & 31) * 4;
        float4 v = *(const float4*)(Qb + (size_t)(q0 + q) * D + k4);
        sQ[(k4 + 0) * 64 + q] = v.x * scale;
        sQ[(k4 + 1) * 64 + q] = v.y * scale;
        sQ[(k4 + 2) * 64 + q] = v.z * scale;
        sQ[(k4 + 3) * 64 + q] = v.w * scale;
    }
    if (tid < 64) { sMx[tid] = -1e30f; sL[tid] = 0.f; }

    const int tq = tid >> 4;   // 0..15
    const int tx = tid & 15;   // 0..15
    const int qb = tq * 4;     // this thread's 4 query rows (both phases)
    const int jb = tx * 4;     // score cols
    const int db = tx * 8;     // PV output cols

    float o[4][8];
#pragma unroll
    for (int i = 0; i < 4; ++i)
#pragma unroll
        for (int j = 0; j < 8; ++j) o[i][j] = 0.f;

    for (int j0 = 0; j0 < S; j0 += 64) {
        __syncthreads();  // prev PV done with sV/sS; also covers init
        // Load K (transposed) and V tiles
        for (int idx = tid; idx < 64 * 32; idx += 256) {
            int j = idx >> 5;
            int k4 = (idx & 31) * 4;
            float4 kv = *(const float4*)(Kb + (size_t)(j0 + j) * D + k4);
            sK[(k4 + 0) * 64 + j] = kv.x;
            sK[(k4 + 1) * 64 + j] = kv.y;
            sK[(k4 + 2) * 64 + j] = kv.z;
            sK[(k4 + 3) * 64 + j] = kv.w;
            float4 vv = *(const float4*)(Vb + (size_t)(j0 + j) * D + k4);
            *(float4*)&sV[j * 128 + k4] = vv;
        }
        __syncthreads();

        // Scores: 4x4 per thread over k=128
        float acc[4][4];
#pragma unroll
        for (int i = 0; i < 4; ++i)
#pragma unroll
            for (int j = 0; j < 4; ++j) acc[i][j] = 0.f;
#pragma unroll 4
        for (int k = 0; k < 128; ++k) {
            float4 qa = *(const float4*)&sQ[k * 64 + qb];
            float4 kb4 = *(const float4*)&sK[k * 64 + jb];
            float aq[4] = {qa.x, qa.y, qa.z, qa.w};
            float bk[4] = {kb4.x, kb4.y, kb4.z, kb4.w};
#pragma unroll
            for (int i = 0; i < 4; ++i)
#pragma unroll
                for (int j = 0; j < 4; ++j)
                    acc[i][j] += aq[i] * bk[j];
        }
#pragma unroll
        for (int i = 0; i < 4; ++i) {
            float4 v;
            v.x = (j0 + jb + 0 < len) ? acc[i][0] : -1e30f;
            v.y = (j0 + jb + 1 < len) ? acc[i][1] : -1e30f;
            v.z = (j0 + jb + 2 < len) ? acc[i][2] : -1e30f;
            v.w = (j0 + jb + 3 < len) ? acc[i][3] : -1e30f;
            *(float4*)&sS[(qb + i) * 64 + jb] = v;
        }
        __syncthreads();

        // Online softmax: 4 threads per row, 16 cols each
        {
            int row = tid >> 2;
            float* sr = &sS[row * 64 + (tid & 3) * 16];
            float mx = sr[0];
#pragma unroll
            for (int j = 1; j < 16; ++j) mx = fmaxf(mx, sr[j]);
            mx = fmaxf(mx, __shfl_xor_sync(0xffffffffu, mx, 1));
            mx = fmaxf(mx, __shfl_xor_sync(0xffffffffu, mx, 2));
            float mold = sMx[row];
            float mnew = fmaxf(mold, mx);
            float sum = 0.f;
#pragma unroll
            for (int j = 0; j < 16; ++j) {
                float pv = __expf(sr[j] - mnew);
                sr[j] = pv;
                sum += pv;
            }
            sum += __shfl_xor_sync(0xffffffffu, sum, 1);
            sum += __shfl_xor_sync(0xffffffffu, sum, 2);
            if ((tid & 3) == 0) {
                float alpha = __expf(mold - mnew);
                sL[row] = sL[row] * alpha + sum;
                sMx[row] = mnew;
                sAl[row] = alpha;
            }
        }
        __syncthreads();

        // Rescale O, accumulate P @ V
        float al[4];
#pragma unroll
        for (int i = 0; i < 4; ++i) al[i] = sAl[qb + i];
#pragma unroll
        for (int i = 0; i < 4; ++i)
#pragma unroll
            for (int j = 0; j < 8; ++j) o[i][j] *= al[i];
#pragma unroll 2
        for (int j = 0; j < 64; ++j) {
            float4 v0 = *(const float4*)&sV[j * 128 + db];
            float4 v1 = *(const float4*)&sV[j * 128 + db + 4];
            float pr[4];
#pragma unroll
            for (int i = 0; i < 4; ++i) pr[i] = sS[(qb + i) * 64 + j];
#pragma unroll
            for (int i = 0; i < 4; ++i) {
                o[i][0] += pr[i] * v0.x; o[i][1] += pr[i] * v0.y;
                o[i][2] += pr[i] * v0.z; o[i][3] += pr[i] * v0.w;
                o[i][4] += pr[i] * v1.x; o[i][5] += pr[i] * v1.y;
                o[i][6] += pr[i] * v1.z; o[i][7] += pr[i] * v1.w;
            }
        }
    }

    // Epilogue: normalize and write
#pragma unroll
    for (int i = 0; i < 4; ++i) {
        float li = sL[qb + i];
        float linv = 1.0f / li;
        float* op = Og + (size_t)(b * S + q0 + qb + i) * D + h * HD + db;
        float4 w0 = make_float4(o[i][0] * linv, o[i][1] * linv,
                                o[i][2] * linv, o[i][3] * linv);
        float4 w1 = make_float4(o[i][4] * linv, o[i][5] * linv,
                                o[i][6] * linv, o[i][7] * linv);
        *(float4*)op = w0;
        *(float4*)(op + 4) = w1;
    }
}

// ---------------------------------------------------------------------------
extern "C" void kernel_launch(void* const* d_in, const int* in_sizes, int n_in,
                              void* d_out, int out_size) {
    (void)in_sizes; (void)n_in; (void)out_size;
    const float* x        = (const float*)d_in[0];
    const int*   seq_lens = (const int*)  d_in[1];
    const float* freqs    = (const float*)d_in[2];
    const float* wq       = (const float*)d_in[3];
    const float* bq       = (const float*)d_in[4];
    const float* wk       = (const float*)d_in[5];
    const float* bk       = (const float*)d_in[6];
    const float* wv       = (const float*)d_in[7];
    const float* bv       = (const float*)d_in[8];
    const float* wo       = (const float*)d_in[9];
    const float* bo       = (const float*)d_in[10];
    const float* gq       = (const float*)d_in[11];
    const float* gk       = (const float*)d_in[12];
    float* out = (float*)d_out;

    float *pq, *pk, *pv, *po;
    cudaGetSymbolAddress((void**)&pq, g_q);
    cudaGetSymbolAddress((void**)&pk, g_k);
    cudaGetSymbolAddress((void**)&pv, g_v);
    cudaGetSymbolAddress((void**)&po, g_o);

    dim3 ggrid(D / 128, M_ROWS / 128);  // (16, 32)
    gemm_nt_bias<<<ggrid, 256>>>(x, wq, bq, pq, D, D);
    gemm_nt_bias<<<ggrid, 256>>>(x, wk, bk, pk, D, D);
    gemm_nt_bias<<<ggrid, 256>>>(x, wv, bv, pv, D, D);

    rmsnorm_rope<<<M_ROWS, 256>>>(pq, gq, freqs);
    rmsnorm_rope<<<M_ROWS, 256>>>(pk, gk, freqs);

    cudaFuncSetAttribute(flash_attn, cudaFuncAttributeMaxDynamicSharedMemorySize,
                         ATTN_SMEM_BYTES);
    flash_attn<<<dim3(S / 64, B * NH), 256, ATTN_SMEM_BYTES>>>(
        pq, pk, pv, seq_lens, po);

    gemm_nt_bias<<<ggrid, 256>>>(po, wo, bo, out, D, D);
}

// round 3
// speedup vs baseline: 4.7656x; 4.7656x over previous
#include <cuda_runtime.h>
#include <math.h>
#include <stdint.h>

#define B 2
#define S 2048
#define D 2048
#define NH 16
#define HD 128
#define M_ROWS (B * S)

// Scratch (allocation-free rule: __device__ globals)
__device__ float g_q[(size_t)M_ROWS * D];
__device__ float g_k[(size_t)M_ROWS * D];
__device__ float g_v[(size_t)M_ROWS * D];
__device__ float g_o[(size_t)M_ROWS * D];
__device__ float g_x[(size_t)M_ROWS * D];
__device__ float g_w[4][(size_t)D * D];

// ---------------------------------------------------------------------------
// helpers
// ---------------------------------------------------------------------------
__device__ __forceinline__ float tf32r(float x) {
    uint32_t u;
    asm("cvt.rna.tf32.f32 %0, %1;" : "=r"(u) : "f"(x));
    return __uint_as_float(u);
}

__device__ __forceinline__ void cpa16(uint32_t saddr, const void* gptr) {
    asm volatile("cp.async.cg.shared.global [%0], [%1], 16;\n"
                 :: "r"(saddr), "l"(gptr));
}
#define CP_COMMIT asm volatile("cp.async.commit_group;\n")
#define CP_WAIT(n) asm volatile("cp.async.wait_group %0;\n" :: "n"(n))

__device__ __forceinline__ void mma_tf32(float* c, const float* a, const float* b) {
    const uint32_t* A = reinterpret_cast<const uint32_t*>(a);
    const uint32_t* Bv = reinterpret_cast<const uint32_t*>(b);
    asm volatile(
        "mma.sync.aligned.m16n8k8.row.col.f32.tf32.tf32.f32 "
        "{%0,%1,%2,%3},{%4,%5,%6,%7},{%8,%9},{%0,%1,%2,%3};\n"
        : "+f"(c[0]), "+f"(c[1]), "+f"(c[2]), "+f"(c[3])
        : "r"(A[0]), "r"(A[1]), "r"(A[2]), "r"(A[3]), "r"(Bv[0]), "r"(Bv[1]));
}

// ---------------------------------------------------------------------------
// elementwise tf32 rna pre-rounding
// ---------------------------------------------------------------------------
__global__ void round_k(const float* __restrict__ src, float* __restrict__ dst, int n4) {
    int i = blockIdx.x * 256 + threadIdx.x;
    if (i < n4) {
        float4 v = ((const float4*)src)[i];
        v.x = tf32r(v.x); v.y = tf32r(v.y); v.z = tf32r(v.z); v.w = tf32r(v.w);
        ((float4*)dst)[i] = v;
    }
}

// ---------------------------------------------------------------------------
// C[M=4096,N=2048] = A[M,K=2048] @ W[N,K]^T + bias   (tf32 tensor-core)
// CTA tile 128x256, BK=32, 8 warps of 64x64, 3-stage cp.async pipeline.
// smem layout per row of 32 floats: element (r,k) at r*32 + ((k>>2 ^ (r&7))<<2) + (k&3)
// ---------------------------------------------------------------------------
#define GEMM_SMEM_BYTES (3 * (128 * 32 + 256 * 32) * 4)

__global__ __launch_bounds__(256) void gemm_tf32(
    const float* __restrict__ A, const float* __restrict__ Wt,
    const float* __restrict__ bias, float* __restrict__ C, int round_out)
{
    extern __shared__ float smg[];
    float* As = smg;                    // [3][128*32]
    float* Bs = smg + 3 * 128 * 32;     // [3][256*32]
    const int tid = threadIdx.x;
    const int lane = tid & 31, w = tid >> 5;
    const int g = lane >> 2, tig = lane & 3;
    const int wm = w >> 2, wn = w & 3;
    const int bm = blockIdx.y * 128, bn = blockIdx.x * 256;

    // cp.async mapping: thread handles rows (ar + 32i), float4-col ac4
    const int ar = tid >> 3;        // 0..31
    const int ac4 = tid & 7;
    const int aswz = ((ac4 ^ (ar & 7)) << 2);   // constant per thread (row&7 invariant)

    const float* Ag = A  + (size_t)(bm + ar) * D + (ac4 << 2);
    const float* Bg = Wt + (size_t)(bn + ar) * D + (ac4 << 2);
    const uint32_t as_b = (uint32_t)__cvta_generic_to_shared(As);
    const uint32_t bs_b = (uint32_t)__cvta_generic_to_shared(Bs);

    float acc[4][8][4];
#pragma unroll
    for (int mt = 0; mt < 4; ++mt)
#pragma unroll
        for (int nt = 0; nt < 8; ++nt)
#pragma unroll
            for (int e = 0; e < 4; ++e) acc[mt][nt][e] = 0.f;

#define G_FILL(st, k0)                                                          \
    do {                                                                        \
        _Pragma("unroll")                                                       \
        for (int i = 0; i < 4; ++i)                                             \
            cpa16(as_b + (((st) * 4096 + (ar + 32 * i) * 32 + aswz) << 2),      \
                  Ag + (size_t)(32 * i) * D + (k0));                            \
        _Pragma("unroll")                                                       \
        for (int i = 0; i < 8; ++i)                                             \
            cpa16(bs_b + (((st) * 8192 + (ar + 32 * i) * 32 + aswz) << 2),      \
                  Bg + (size_t)(32 * i) * D + (k0));                            \
    } while (0)

    G_FILL(0, 0);  CP_COMMIT;
    G_FILL(1, 32); CP_COMMIT;

    const int ra = wm * 64 + g;   // + mt*16 (+8)
    const int rb = wn * 64 + g;   // + nt*8

    for (int kt = 0; kt < 64; ++kt) {
        CP_WAIT(1);
        __syncthreads();
        if (kt + 2 < 64) {
            int st2 = (kt + 2) % 3;
            G_FILL(st2, (kt + 2) * 32);
        }
        CP_COMMIT;
        const float* as = As + (kt % 3) * 4096;
        const float* bs = Bs + (kt % 3) * 8192;
#pragma unroll
        for (int ks = 0; ks < 4; ++ks) {
            const int cs0 = (((2 * ks)     ^ g) << 2) + tig;
            const int cs1 = (((2 * ks + 1) ^ g) << 2) + tig;
            float a[4][4], bq[8][2];
#pragma unroll
            for (int mt = 0; mt < 4; ++mt) {
                int r0 = (ra + mt * 16) * 32;
                a[mt][0] = as[r0 + cs0];       a[mt][1] = as[r0 + 256 + cs0];
                a[mt][2] = as[r0 + cs1];       a[mt][3] = as[r0 + 256 + cs1];
            }
#pragma unroll
            for (int nt = 0; nt < 8; ++nt) {
                int r0 = (rb + nt * 8) * 32;
                bq[nt][0] = bs[r0 + cs0];      bq[nt][1] = bs[r0 + cs1];
            }
#pragma unroll
            for (int mt = 0; mt < 4; ++mt)
#pragma unroll
                for (int nt = 0; nt < 8; ++nt)
                    mma_tf32(acc[mt][nt], a[mt], bq[nt]);
        }
    }

    // epilogue
#pragma unroll
    for (int mt = 0; mt < 4; ++mt) {
        int r0 = bm + wm * 64 + mt * 16 + g;
#pragma unroll
        for (int nt = 0; nt < 8; ++nt) {
            int c = bn + wn * 64 + nt * 8 + 2 * tig;
            float b0 = bias[c], b1 = bias[c + 1];
            float2 v0 = make_float2(acc[mt][nt][0] + b0, acc[mt][nt][1] + b1);
            float2 v1 = make_float2(acc[mt][nt][2] + b0, acc[mt][nt][3] + b1);
            if (round_out) {
                v0.x = tf32r(v0.x); v0.y = tf32r(v0.y);
                v1.x = tf32r(v1.x); v1.y = tf32r(v1.y);
            }
            *(float2*)(C + (size_t)r0 * D + c) = v0;
            *(float2*)(C + (size_t)(r0 + 8) * D + c) = v1;
        }
    }
#undef G_FILL
}

// ---------------------------------------------------------------------------
// Fused RMSNorm (full D) * g + per-head RoPE, in place, tf32-rounded output.
// ---------------------------------------------------------------------------
__global__ __launch_bounds__(256) void rmsnorm_rope(
    float* __restrict__ t, const float* __restrict__ gw,
    const float* __restrict__ freqs)
{
    const int row = blockIdx.x;
    const int s = row & (S - 1);
    const int tid = threadIdx.x;
    float* p = t + (size_t)row * D;

    float4 v0 = *(const float4*)(p + tid * 8);
    float4 v1 = *(const float4*)(p + tid * 8 + 4);
    float ss = v0.x * v0.x + v0.y * v0.y + v0.z * v0.z + v0.w * v0.w
             + v1.x * v1.x + v1.y * v1.y + v1.z * v1.z + v1.w * v1.w;

    __shared__ float red[256];
    red[tid] = ss;
    __syncthreads();
    for (int off = 128; off > 0; off >>= 1) {
        if (tid < off) red[tid] += red[tid + off];
        __syncthreads();
    }
    const float inv = rsqrtf(red[0] / (float)D + 1e-6f);

    float4 g0 = *(const float4*)(gw + tid * 8);
    float4 g1 = *(const float4*)(gw + tid * 8 + 4);
    float u[8];
    u[0] = v0.x * inv * g0.x; u[1] = v0.y * inv * g0.y;
    u[2] = v0.z * inv * g0.z; u[3] = v0.w * inv * g0.w;
    u[4] = v1.x * inv * g1.x; u[5] = v1.y * inv * g1.y;
    u[6] = v1.z * inv * g1.z; u[7] = v1.w * inv * g1.w;

    float r[8];
#pragma unroll
    for (int j = 0; j < 4; ++j) {
        int pidx = tid * 4 + j;
        int i = pidx & 63;
        float sn, cs;
        sincosf(freqs[(size_t)s * 64 + i], &sn, &cs);
        float re = u[2 * j], im = u[2 * j + 1];
        r[2 * j]     = tf32r(re * cs - im * sn);
        r[2 * j + 1] = tf32r(re * sn + im * cs);
    }
    *(float4*)(p + tid * 8)     = make_float4(r[0], r[1], r[2], r[3]);
    *(float4*)(p + tid * 8 + 4) = make_float4(r[4], r[5], r[6], r[7]);
}

// ---------------------------------------------------------------------------
// Flash attention, tf32 tensor-core. CTA: 128 q rows x (b,h); 8 warps, each
// owns 16 q rows end-to-end. Q kept in registers; K/V double-buffered cp.async.
// smem floats: [0,16384) K stages, [16384,32768) V stages, [32768,40960) P.
// ---------------------------------------------------------------------------
#define FA_SMEM_BYTES (40960 * 4)

__global__ __launch_bounds__(256) void flash_tf32(
    const float* __restrict__ Qg, const float* __restrict__ Kg,
    const float* __restrict__ Vg, const int* __restrict__ seq_lens,
    float* __restrict__ Og)
{
    extern __shared__ float smf[];
    const int tid = threadIdx.x, lane = tid & 31, w = tid >> 5;
    const int g = lane >> 2, tig = lane & 3;
    const int bh = blockIdx.y, b = bh >> 4, h = bh & 15;
    const int q0 = blockIdx.x * 128;
    const int len = seq_lens[b];
    const float scale = 0.088388347648318447f;  // 1/sqrt(128)

    const float* Qb = Qg + (size_t)b * S * D + h * HD;
    const float* Kb = Kg + (size_t)b * S * D + h * HD;
    const float* Vb = Vg + (size_t)b * S * D + h * HD;
    const uint32_t sb = (uint32_t)__cvta_generic_to_shared(smf);

    const int fr  = tid >> 5;    // 0..7 (row&7 invariant under +8i)
    const int fc4 = tid & 31;
    const int ksw = ((fc4 ^ fr) << 2);             // K/Q/P-style swizzle
    const int vsw = ((fc4 ^ (2 * (fr & 3))) << 2); // V-style swizzle

    // ---- Q prologue: cp.async into [0, 16384) then load frags to regs ----
#pragma unroll
    for (int i = 0; i < 16; ++i) {
        int r = fr + 8 * i;
        cpa16(sb + ((r * 128 + ksw) << 2), Qb + (size_t)(q0 + r) * D + (fc4 << 2));
    }
    CP_COMMIT;
    CP_WAIT(0);
    __syncthreads();

    float q[16][4];
    {
        int r0 = (w * 16 + g) * 128;
#pragma unroll
        for (int ks = 0; ks < 16; ++ks) {
            int cs0 = (((2 * ks)     ^ g) << 2) + tig;
            int cs1 = (((2 * ks + 1) ^ g) << 2) + tig;
            q[ks][0] = smf[r0 + cs0];        q[ks][1] = smf[r0 + 1024 + cs0];
            q[ks][2] = smf[r0 + cs1];        q[ks][3] = smf[r0 + 1024 + cs1];
        }
    }
    __syncthreads();

#define KV_FILL(st, j0)                                                         \
    do {                                                                        \
        _Pragma("unroll")                                                       \
        for (int i = 0; i < 8; ++i) {                                           \
            int r = fr + 8 * i;                                                 \
            cpa16(sb + (((st) * 8192 + r * 128 + ksw) << 2),                    \
                  Kb + (size_t)((j0) + r) * D + (fc4 << 2));                    \
        }                                                                       \
        _Pragma("unroll")                                                       \
        for (int i = 0; i < 8; ++i) {                                           \
            int r = fr + 8 * i;                                                 \
            cpa16(sb + ((16384 + (st) * 8192 + r * 128 + vsw) << 2),            \
                  Vb + (size_t)((j0) + r) * D + (fc4 << 2));                    \
        }                                                                       \
    } while (0)

    KV_FILL(0, 0);  CP_COMMIT;
    KV_FILL(1, 64); CP_COMMIT;

    float o[16][4];
#pragma unroll
    for (int nt = 0; nt < 16; ++nt)
#pragma unroll
        for (int e = 0; e < 4; ++e) o[nt][e] = 0.f;
    float m0 = -1e30f, m1 = -1e30f, l0 = 0.f, l1 = 0.f;
    const int prow0 = 32768 + (w * 16 + g) * 64;

    for (int t = 0; t < 32; ++t) {
        CP_WAIT(1);
        __syncthreads();
        const int st = t & 1;
        const float* ksm = smf + st * 8192;
        const float* vsm = smf + 16384 + st * 8192;

        // ---- S = Q @ K^T ----
        float s[8][4];
#pragma unroll
        for (int nt = 0; nt < 8; ++nt)
#pragma unroll
            for (int e = 0; e < 4; ++e) s[nt][e] = 0.f;
#pragma unroll
        for (int ks = 0; ks < 16; ++ks) {
            int cs0 = (((2 * ks)     ^ g) << 2) + tig;
            int cs1 = (((2 * ks + 1) ^ g) << 2) + tig;
            float bf[8][2];
#pragma unroll
            for (int nt = 0; nt < 8; ++nt) {
                int r0 = (nt * 8 + g) * 128;
                bf[nt][0] = ksm[r0 + cs0];
                bf[nt][1] = ksm[r0 + cs1];
            }
#pragma unroll
            for (int nt = 0; nt < 8; ++nt)
                mma_tf32(s[nt], q[ks], bf[nt]);
        }

        const int j0 = t * 64;
        if (j0 + 64 > len) {
#pragma unroll
            for (int nt = 0; nt < 8; ++nt) {
                int c = j0 + nt * 8 + 2 * tig;
                if (c     >= len) { s[nt][0] = -1e30f; s[nt][2] = -1e30f; }
                if (c + 1 >= len) { s[nt][1] = -1e30f; s[nt][3] = -1e30f; }
            }
        }

        // ---- online softmax (rows g and g+8, replicated over tig quad) ----
        float mx0 = -1e30f, mx1 = -1e30f;
#pragma unroll
        for (int nt = 0; nt < 8; ++nt) {
            mx0 = fmaxf(mx0, fmaxf(s[nt][0], s[nt][1]));
            mx1 = fmaxf(mx1, fmaxf(s[nt][2], s[nt][3]));
        }
        mx0 = fmaxf(mx0, __shfl_xor_sync(0xffffffffu, mx0, 1));
        mx0 = fmaxf(mx0, __shfl_xor_sync(0xffffffffu, mx0, 2));
        mx1 = fmaxf(mx1, __shfl_xor_sync(0xffffffffu, mx1, 1));
        mx1 = fmaxf(mx1, __shfl_xor_sync(0xffffffffu, mx1, 2));
        float mn0 = fmaxf(m0, mx0), mn1 = fmaxf(m1, mx1);
        float al0 = __expf(scale * (m0 - mn0));
        float al1 = __expf(scale * (m1 - mn1));
        float sum0 = 0.f, sum1 = 0.f;
#pragma unroll
        for (int nt = 0; nt < 8; ++nt) {
            s[nt][0] = __expf(scale * (s[nt][0] - mn0)); sum0 += s[nt][0];
            s[nt][1] = __expf(scale * (s[nt][1] - mn0)); sum0 += s[nt][1];
            s[nt][2] = __expf(scale * (s[nt][2] - mn1)); sum1 += s[nt][2];
            s[nt][3] = __expf(scale * (s[nt][3] - mn1)); sum1 += s[nt][3];
        }
        sum0 += __shfl_xor_sync(0xffffffffu, sum0, 1);
        sum0 += __shfl_xor_sync(0xffffffffu, sum0, 2);
        sum1 += __shfl_xor_sync(0xffffffffu, sum1, 1);
        sum1 += __shfl_xor_sync(0xffffffffu, sum1, 2);
        l0 = l0 * al0 + sum0; l1 = l1 * al1 + sum1;
        m0 = mn0; m1 = mn1;
#pragma unroll
        for (int nt = 0; nt < 16; ++nt) {
            o[nt][0] *= al0; o[nt][1] *= al0;
            o[nt][2] *= al1; o[nt][3] *= al1;
        }

        // ---- write P to per-warp smem slab ----
#pragma unroll
        for (int nt = 0; nt < 8; ++nt) {
            int c4 = 2 * nt + (tig >> 1);
            int off = ((c4 ^ g) << 2) + ((2 * tig) & 3);
            *(float2*)&smf[prow0 + off]       = make_float2(s[nt][0], s[nt][1]);
            *(float2*)&smf[prow0 + 512 + off] = make_float2(s[nt][2], s[nt][3]);
        }
        __syncwarp();

        // ---- O += P @ V ----
#pragma unroll
        for (int ks = 0; ks < 8; ++ks) {
            int cs0 = (((2 * ks)     ^ g) << 2) + tig;
            int cs1 = (((2 * ks + 1) ^ g) << 2) + tig;
            float a[4];
            a[0] = smf[prow0 + cs0];       a[1] = smf[prow0 + 512 + cs0];
            a[2] = smf[prow0 + cs1];       a[3] = smf[prow0 + 512 + cs1];
            int vr0 = (8 * ks + tig) * 128;
            int vr1 = (8 * ks + tig + 4) * 128;
#pragma unroll
            for (int nt = 0; nt < 16; ++nt) {
                int c4 = 2 * nt + (g >> 2);
                int cv = ((c4 ^ (2 * tig)) << 2) + (g & 3);
                float bv[2] = { vsm[vr0 + cv], vsm[vr1 + cv] };
                mma_tf32(o[nt], a, bv);
            }
        }

        __syncthreads();
        if (t + 2 < 32) KV_FILL(st, (t + 2) * 64);
        CP_COMMIT;
    }

    // ---- epilogue: normalize, round (O-proj consumes via tf32 mma), store ----
    float li0 = 1.0f / l0, li1 = 1.0f / l1;
    int r0 = q0 + w * 16 + g;
    float* Ob = Og + (size_t)b * S * D + h * HD;
#pragma unroll
    for (int nt = 0; nt < 16; ++nt) {
        int c = nt * 8 + 2 * tig;
        float2 v0 = make_float2(tf32r(o[nt][0] * li0), tf32r(o[nt][1] * li0));
        float2 v1 = make_float2(tf32r(o[nt][2] * li1), tf32r(o[nt][3] * li1));
        *(float2*)(Ob + (size_t)r0 * D + c) = v0;
        *(float2*)(Ob + (size_t)(r0 + 8) * D + c) = v1;
    }
#undef KV_FILL
}

// ---------------------------------------------------------------------------
extern "C" void kernel_launch(void* const* d_in, const int* in_sizes, int n_in,
                              void* d_out, int out_size) {
    (void)in_sizes; (void)n_in; (void)out_size;
    const float* x        = (const float*)d_in[0];
    const int*   seq_lens = (const int*)  d_in[1];
    const float* freqs    = (const float*)d_in[2];
    const float* wq       = (const float*)d_in[3];
    const float* bq       = (const float*)d_in[4];
    const float* wk       = (const float*)d_in[5];
    const float* bk       = (const float*)d_in[6];
    const float* wv       = (const float*)d_in[7];
    const float* bv       = (const float*)d_in[8];
    const float* wo       = (const float*)d_in[9];
    const float* bo       = (const float*)d_in[10];
    const float* gq       = (const float*)d_in[11];
    const float* gk       = (const float*)d_in[12];
    float* out = (float*)d_out;

    float *pq, *pk, *pv, *po, *px, *pw;
    cudaGetSymbolAddress((void**)&pq, g_q);
    cudaGetSymbolAddress((void**)&pk, g_k);
    cudaGetSymbolAddress((void**)&pv, g_v);
    cudaGetSymbolAddress((void**)&po, g_o);
    cudaGetSymbolAddress((void**)&px, g_x);
    cudaGetSymbolAddress((void**)&pw, g_w);
    float* pw0 = pw;
    float* pw1 = pw + (size_t)D * D;
    float* pw2 = pw + 2 * (size_t)D * D;
    float* pw3 = pw + 3 * (size_t)D * D;

    cudaFuncSetAttribute(gemm_tf32, cudaFuncAttributeMaxDynamicSharedMemorySize,
                         GEMM_SMEM_BYTES);
    cudaFuncSetAttribute(flash_tf32, cudaFuncAttributeMaxDynamicSharedMemorySize,
                         FA_SMEM_BYTES);

    // pre-round inputs to tf32 (rna) so cp.async paths carry rounded data
    round_k<<<(M_ROWS * D / 4 + 255) / 256, 256>>>(x, px, M_ROWS * D / 4);
    round_k<<<(D * D / 4 + 255) / 256, 256>>>(wq, pw0, D * D / 4);
    round_k<<<(D * D / 4 + 255) / 256, 256>>>(wk, pw1, D * D / 4);
    round_k<<<(D * D / 4 + 255) / 256, 256>>>(wv, pw2, D * D / 4);
    round_k<<<(D * D / 4 + 255) / 256, 256>>>(wo, pw3, D * D / 4);

    dim3 ggrid(D / 256, M_ROWS / 128);  // (8, 32)
    gemm_tf32<<<ggrid, 256, GEMM_SMEM_BYTES>>>(px, pw0, bq, pq, 0);
    gemm_tf32<<<ggrid, 256, GEMM_SMEM_BYTES>>>(px, pw1, bk, pk, 0);
    gemm_tf32<<<ggrid, 256, GEMM_SMEM_BYTES>>>(px, pw2, bv, pv, 1);

    rmsnorm_rope<<<M_ROWS, 256>>>(pq, gq, freqs);
    rmsnorm_rope<<<M_ROWS, 256>>>(pk, gk, freqs);

    flash_tf32<<<dim3(S / 128, B * NH), 256, FA_SMEM_BYTES>>>(
        pq, pk, pv, seq_lens, po);

    gemm_tf32<<<ggrid, 256, GEMM_SMEM_BYTES>>>(po, pw3, bo, out, 0);
}

// round 5
// speedup vs baseline: 8.0136x; 1.6816x over previous
#include <cuda_runtime.h>
#include <cuda_fp16.h>
#include <math.h>
#include <stdint.h>

#define B 2
#define S 2048
#define D 2048
#define NH 16
#define HD 128
#define M_ROWS (B * S)

// Scratch (allocation-free rule: __device__ globals), fp16 operands
__device__ __half g_xh[(size_t)M_ROWS * D];
__device__ __half g_wh[4][(size_t)D * D];
__device__ __half g_qh[(size_t)M_ROWS * D];
__device__ __half g_kh[(size_t)M_ROWS * D];
__device__ __half g_vh[(size_t)M_ROWS * D];
__device__ __half g_oh[(size_t)M_ROWS * D];

// ---------------------------------------------------------------------------
// primitives
// ---------------------------------------------------------------------------
__device__ __forceinline__ void cpa16(uint32_t saddr, const void* gptr) {
    asm volatile("cp.async.cg.shared.global [%0], [%1], 16;\n"
                 :: "r"(saddr), "l"(gptr));
}
#define CP_COMMIT asm volatile("cp.async.commit_group;\n")
#define CP_WAIT(n) asm volatile("cp.async.wait_group %0;\n" :: "n"(n))

__device__ __forceinline__ void ldm_x4(uint32_t* r, uint32_t a) {
    asm volatile("ldmatrix.sync.aligned.m8n8.x4.shared.b16 {%0,%1,%2,%3}, [%4];"
                 : "=r"(r[0]), "=r"(r[1]), "=r"(r[2]), "=r"(r[3]) : "r"(a));
}
__device__ __forceinline__ void ldm_x4t(uint32_t* r, uint32_t a) {
    asm volatile("ldmatrix.sync.aligned.m8n8.x4.trans.shared.b16 {%0,%1,%2,%3}, [%4];"
                 : "=r"(r[0]), "=r"(r[1]), "=r"(r[2]), "=r"(r[3]) : "r"(a));
}
__device__ __forceinline__ void mma_f16(float* c, const uint32_t* a,
                                        uint32_t b0, uint32_t b1) {
    asm volatile(
        "mma.sync.aligned.m16n8k16.row.col.f32.f16.f16.f32 "
        "{%0,%1,%2,%3},{%4,%5,%6,%7},{%8,%9},{%0,%1,%2,%3};\n"
        : "+f"(c[0]), "+f"(c[1]), "+f"(c[2]), "+f"(c[3])
        : "r"(a[0]), "r"(a[1]), "r"(a[2]), "r"(a[3]), "r"(b0), "r"(b1));
}

// ---------------------------------------------------------------------------
// f32 -> f16 conversion (4 elems/thread)
// ---------------------------------------------------------------------------
__global__ void conv_h(const float* __restrict__ src, __half* __restrict__ dst, int n4) {
    int i = blockIdx.x * 256 + threadIdx.x;
    if (i < n4) {
        float4 v = ((const float4*)src)[i];
        __half2 h0 = __floats2half2_rn(v.x, v.y);
        __half2 h1 = __floats2half2_rn(v.z, v.w);
        ((uint2*)dst)[i] = make_uint2(*(uint32_t*)&h0, *(uint32_t*)&h1);
    }
}

// ---------------------------------------------------------------------------
// fp16 GEMM: C[M,N=2048] = A[M,K=2048] @ W[N,K]^T + bias. fp32 accumulate.
// CTA 128x256, 8 warps (64x64), BK=64 halves (128B rows), 3-stage cp.async.
// smem stage s at s*49152: A 128x128B, B 256x128B at +16384.
// out_f32: 1 -> write float C (final), 0 -> write half C.
// ---------------------------------------------------------------------------
#define GEMM_SMEM_BYTES (3 * 49152)

__global__ __launch_bounds__(256) void gemm_f16(
    const __half* __restrict__ A, const __half* __restrict__ Wt,
    const float* __restrict__ bias, __half* __restrict__ Ch,
    float* __restrict__ Cf, int out_f32)
{
    extern __shared__ char smg[];
    const uint32_t sb = (uint32_t)__cvta_generic_to_shared(smg);
    const int tid = threadIdx.x, lane = tid & 31, w = tid >> 5;
    const int g = lane >> 2, tig = lane & 3;
    const int wm = w >> 2, wn = w & 3;           // wm 0..1, wn 0..3
    const int bm = blockIdx.y * 128, bn = blockIdx.x * 256;

    // ldmatrix lane geometry
    const int tl = lane >> 3, lr = lane & 7;
    const int rowoff = ((tl & 1) << 3) + lr;     // 0..15
    const int kadd = tl >> 1;                    // 0..1

    // fill geometry: id = tid + 256*i -> row = id>>3, c16 = id&7
    const int fro = tid >> 3, fc16 = tid & 7;

    float acc[4][8][4];
#pragma unroll
    for (int mt = 0; mt < 4; ++mt)
#pragma unroll
        for (int nt = 0; nt < 8; ++nt)
#pragma unroll
            for (int e = 0; e < 4; ++e) acc[mt][nt][e] = 0.f;

#define GF(st, kt)                                                              \
    do {                                                                        \
        const int k0h = (kt) * 64;                                              \
        _Pragma("unroll")                                                       \
        for (int i = 0; i < 4; ++i) {                                           \
            int row = fro + 32 * i;                                             \
            cpa16(sb + (st) * 49152 + row * 128 + ((fc16 ^ (row & 7)) << 4),    \
                  A + (size_t)(bm + row) * D + k0h + fc16 * 8);                 \
        }                                                                       \
        _Pragma("unroll")                                                       \
        for (int i = 0; i < 8; ++i) {                                           \
            int row = fro + 32 * i;                                             \
            cpa16(sb + (st) * 49152 + 16384 + row * 128                         \
                      + ((fc16 ^ (row & 7)) << 4),                              \
                  Wt + (size_t)(bn + row) * D + k0h + fc16 * 8);                \
        }                                                                       \
    } while (0)

    GF(0, 0); CP_COMMIT;
    GF(1, 1); CP_COMMIT;
    GF(2, 2); CP_COMMIT;

    for (int kt = 0; kt < 32; ++kt) {
        CP_WAIT(2);
        __syncthreads();
        const uint32_t as = sb + (kt % 3) * 49152;
        const uint32_t bs = as + 16384;
#pragma unroll
        for (int ks = 0; ks < 4; ++ks) {
            const int c16 = 2 * ks + kadd;
            uint32_t af[4][4], bf[4][4];
#pragma unroll
            for (int mt = 0; mt < 4; ++mt) {
                int row = wm * 64 + mt * 16 + rowoff;
                ldm_x4(af[mt], as + row * 128 + ((c16 ^ (row & 7)) << 4));
            }
#pragma unroll
            for (int np = 0; np < 4; ++np) {
                int row = wn * 64 + np * 16 + rowoff;
                ldm_x4(bf[np], bs + row * 128 + ((c16 ^ (row & 7)) << 4));
            }
#pragma unroll
            for (int mt = 0; mt < 4; ++mt)
#pragma unroll
                for (int np = 0; np < 4; ++np) {
                    mma_f16(acc[mt][2 * np],     af[mt], bf[np][0], bf[np][2]);
                    mma_f16(acc[mt][2 * np + 1], af[mt], bf[np][1], bf[np][3]);
                }
        }
        __syncthreads();
        if (kt + 3 < 32) { GF(kt % 3, kt + 3); }
        CP_COMMIT;
    }

    // epilogue
#pragma unroll
    for (int mt = 0; mt < 4; ++mt) {
        int r0 = bm + wm * 64 + mt * 16 + g;
#pragma unroll
        for (int nt = 0; nt < 8; ++nt) {
            int c = bn + wn * 64 + nt * 8 + 2 * tig;
            float b0 = bias[c], b1 = bias[c + 1];
            float v00 = acc[mt][nt][0] + b0, v01 = acc[mt][nt][1] + b1;
            float v10 = acc[mt][nt][2] + b0, v11 = acc[mt][nt][3] + b1;
            if (out_f32) {
                *(float2*)(Cf + (size_t)r0 * D + c) = make_float2(v00, v01);
                *(float2*)(Cf + (size_t)(r0 + 8) * D + c) = make_float2(v10, v11);
            } else {
                __half2 h0 = __floats2half2_rn(v00, v01);
                __half2 h1 = __floats2half2_rn(v10, v11);
                *(__half2*)(Ch + (size_t)r0 * D + c) = h0;
                *(__half2*)(Ch + (size_t)(r0 + 8) * D + c) = h1;
            }
        }
    }
#undef GF
}

// ---------------------------------------------------------------------------
// Fused RMSNorm (full D, fp32 math) * g + per-head RoPE, in place on fp16.
// ---------------------------------------------------------------------------
__global__ __launch_bounds__(256) void rmsnorm_rope_h(
    __half* __restrict__ t, const float* __restrict__ gw,
    const float* __restrict__ freqs)
{
    const int row = blockIdx.x;
    const int s = row & (S - 1);
    const int tid = threadIdx.x;
    __half* p = t + (size_t)row * D;

    uint4 raw = *(const uint4*)(p + tid * 8);
    __half2 h[4] = { *(__half2*)&raw.x, *(__half2*)&raw.y,
                     *(__half2*)&raw.z, *(__half2*)&raw.w };
    float u[8];
#pragma unroll
    for (int j = 0; j < 4; ++j) {
        float2 f = __half22float2(h[j]);
        u[2 * j] = f.x; u[2 * j + 1] = f.y;
    }
    float ss = 0.f;
#pragma unroll
    for (int j = 0; j < 8; ++j) ss += u[j] * u[j];

    __shared__ float red[256];
    red[tid] = ss;
    __syncthreads();
    for (int off = 128; off > 0; off >>= 1) {
        if (tid < off) red[tid] += red[tid + off];
        __syncthreads();
    }
    const float inv = rsqrtf(red[0] / (float)D + 1e-6f);

    float4 g0 = *(const float4*)(gw + tid * 8);
    float4 g1 = *(const float4*)(gw + tid * 8 + 4);
    u[0] *= inv * g0.x; u[1] *= inv * g0.y; u[2] *= inv * g0.z; u[3] *= inv * g0.w;
    u[4] *= inv * g1.x; u[5] *= inv * g1.y; u[6] *= inv * g1.z; u[7] *= inv * g1.w;

    uint4 outw;
    uint32_t* ow = (uint32_t*)&outw;
#pragma unroll
    for (int j = 0; j < 4; ++j) {
        int pidx = tid * 4 + j;
        int i = pidx & 63;
        float sn, cs;
        sincosf(freqs[(size_t)s * 64 + i], &sn, &cs);
        float re = u[2 * j], im = u[2 * j + 1];
        __half2 hv = __floats2half2_rn(re * cs - im * sn, re * sn + im * cs);
        ow[j] = *(uint32_t*)&hv;
    }
    *(uint4*)(p + tid * 8) = outw;
}

// ---------------------------------------------------------------------------
// Flash attention fp16: CTA = 128 q rows x (b,h), 8 warps x 16 rows.
// Q frags from gmem into regs. K,V double-buffered cp.async (64 kv rows).
// smem: K [0,32768) 2 stages, V [32768,65536), P [65536,81920).
// ---------------------------------------------------------------------------
#define FA_SMEM_BYTES 81920

__global__ __launch_bounds__(256) void flash_f16(
    const __half* __restrict__ Qg, const __half* __restrict__ Kg,
    const __half* __restrict__ Vg, const int* __restrict__ seq_lens,
    __half* __restrict__ Og)
{
    extern __shared__ char smf[];
    const uint32_t sb = (uint32_t)__cvta_generic_to_shared(smf);
    const int tid = threadIdx.x, lane = tid & 31, w = tid >> 5;
    const int g = lane >> 2, tig = lane & 3;
    const int bh = blockIdx.y, b = bh >> 4, h = bh & 15;
    const int q0 = blockIdx.x * 128;
    const int len = seq_lens[b];
    const float scale = 0.088388347648318447f;  // 1/sqrt(128)

    const __half* Qb = Qg + (size_t)b * S * D + h * HD;
    const __half* Kb = Kg + (size_t)b * S * D + h * HD;
    const __half* Vb = Vg + (size_t)b * S * D + h * HD;

    const int tl = lane >> 3, lr = lane & 7;
    const int rowoff = ((tl & 1) << 3) + lr;
    const int kadd = tl >> 1;
    const int fro = tid >> 4, fc16 = tid & 15;   // fill: row 0..15(+16i), chunk 0..15

#define KV_FILL(st, j0)                                                         \
    do {                                                                        \
        _Pragma("unroll")                                                       \
        for (int i = 0; i < 4; ++i) {                                           \
            int row = fro + 16 * i;                                             \
            uint32_t soff = (uint32_t)(row * 256 + ((fc16 ^ (row & 7)) << 4));  \
            cpa16(sb + (st) * 16384 + soff,                                     \
                  Kb + (size_t)((j0) + row) * D + fc16 * 8);                    \
            cpa16(sb + 32768 + (st) * 16384 + soff,                             \
                  Vb + (size_t)((j0) + row) * D + fc16 * 8);                    \
        }                                                                       \
    } while (0)

    KV_FILL(0, 0);  CP_COMMIT;
    KV_FILL(1, 64); CP_COMMIT;

    // Q fragments direct from gmem (rows w*16+g, w*16+g+8)
    uint32_t qf[8][4];
    {
        const __half* r0p = Qb + (size_t)(q0 + w * 16 + g) * D;
        const __half* r1p = r0p + (size_t)8 * D;
#pragma unroll
        for (int ks = 0; ks < 8; ++ks) {
            int c = ks * 16 + 2 * tig;
            qf[ks][0] = *(const uint32_t*)(r0p + c);
            qf[ks][1] = *(const uint32_t*)(r1p + c);
            qf[ks][2] = *(const uint32_t*)(r0p + c + 8);
            qf[ks][3] = *(const uint32_t*)(r1p + c + 8);
        }
    }

    float o[16][4];
#pragma unroll
    for (int nt = 0; nt < 16; ++nt)
#pragma unroll
        for (int e = 0; e < 4; ++e) o[nt][e] = 0.f;
    float m0 = -1e30f, m1 = -1e30f, l0 = 0.f, l1 = 0.f;

    const uint32_t pbase = sb + 65536;
    const int prA = w * 16 + g, prB = prA + 8;
    const uint32_t paddrA = pbase + prA * 128;
    const uint32_t paddrB = pbase + prB * 128;

    for (int t = 0; t < 32; ++t) {
        CP_WAIT(1);
        __syncthreads();
        const uint32_t kst = sb + (t & 1) * 16384;
        const uint32_t vst = sb + 32768 + (t & 1) * 16384;

        // ---- S = Q @ K^T  (64 cols = 8 n8 frags) ----
        float s[8][4];
#pragma unroll
        for (int nt = 0; nt < 8; ++nt)
#pragma unroll
            for (int e = 0; e < 4; ++e) s[nt][e] = 0.f;
#pragma unroll
        for (int ks = 0; ks < 8; ++ks) {
            const int c16 = 2 * ks + kadd;
            uint32_t kb[4][4];
#pragma unroll
            for (int np = 0; np < 4; ++np) {
                int row = np * 16 + rowoff;
                ldm_x4(kb[np], kst + row * 256 + ((c16 ^ (row & 7)) << 4));
            }
#pragma unroll
            for (int np = 0; np < 4; ++np) {
                mma_f16(s[2 * np],     qf[ks], kb[np][0], kb[np][2]);
                mma_f16(s[2 * np + 1], qf[ks], kb[np][1], kb[np][3]);
            }
        }

        const int j0 = t * 64;
        if (j0 + 64 > len) {
#pragma unroll
            for (int nt = 0; nt < 8; ++nt) {
                int c = j0 + nt * 8 + 2 * tig;
                if (c     >= len) { s[nt][0] = -1e30f; s[nt][2] = -1e30f; }
                if (c + 1 >= len) { s[nt][1] = -1e30f; s[nt][3] = -1e30f; }
            }
        }

        // ---- online softmax (rows g, g+8) ----
        float mx0 = -1e30f, mx1 = -1e30f;
#pragma unroll
        for (int nt = 0; nt < 8; ++nt) {
            mx0 = fmaxf(mx0, fmaxf(s[nt][0], s[nt][1]));
            mx1 = fmaxf(mx1, fmaxf(s[nt][2], s[nt][3]));
        }
        mx0 = fmaxf(mx0, __shfl_xor_sync(0xffffffffu, mx0, 1));
        mx0 = fmaxf(mx0, __shfl_xor_sync(0xffffffffu, mx0, 2));
        mx1 = fmaxf(mx1, __shfl_xor_sync(0xffffffffu, mx1, 1));
        mx1 = fmaxf(mx1, __shfl_xor_sync(0xffffffffu, mx1, 2));
        float mn0 = fmaxf(m0, mx0), mn1 = fmaxf(m1, mx1);
        float al0 = __expf(scale * (m0 - mn0));
        float al1 = __expf(scale * (m1 - mn1));
        float sum0 = 0.f, sum1 = 0.f;
#pragma unroll
        for (int nt = 0; nt < 8; ++nt) {
            s[nt][0] = __expf(scale * (s[nt][0] - mn0)); sum0 += s[nt][0];
            s[nt][1] = __expf(scale * (s[nt][1] - mn0)); sum0 += s[nt][1];
            s[nt][2] = __expf(scale * (s[nt][2] - mn1)); sum1 += s[nt][2];
            s[nt][3] = __expf(scale * (s[nt][3] - mn1)); sum1 += s[nt][3];
        }
        sum0 += __shfl_xor_sync(0xffffffffu, sum0, 1);
        sum0 += __shfl_xor_sync(0xffffffffu, sum0, 2);
        sum1 += __shfl_xor_sync(0xffffffffu, sum1, 1);
        sum1 += __shfl_xor_sync(0xffffffffu, sum1, 2);
        l0 = l0 * al0 + sum0; l1 = l1 * al1 + sum1;
        m0 = mn0; m1 = mn1;
#pragma unroll
        for (int nt = 0; nt < 16; ++nt) {
            o[nt][0] *= al0; o[nt][1] *= al0;
            o[nt][2] *= al1; o[nt][3] *= al1;
        }

        // ---- P -> per-warp smem (fp16), then A-frags via ldmatrix ----
#pragma unroll
        for (int nt = 0; nt < 8; ++nt) {
            __half2 hA = __floats2half2_rn(s[nt][0], s[nt][1]);
            __half2 hB = __floats2half2_rn(s[nt][2], s[nt][3]);
            uint32_t offA = ((nt ^ (prA & 7)) << 4) + 4 * tig;
            uint32_t offB = ((nt ^ (prB & 7)) << 4) + 4 * tig;
            *(uint32_t*)((char*)smf + (paddrA - sb) + offA) = *(uint32_t*)&hA;
            *(uint32_t*)((char*)smf + (paddrB - sb) + offB) = *(uint32_t*)&hB;
        }
        __syncwarp();

        // ---- O += P @ V ----
#pragma unroll
        for (int ks = 0; ks < 4; ++ks) {
            uint32_t pa[4];
            {
                int row = w * 16 + rowoff;
                int c16 = 2 * ks + kadd;
                ldm_x4(pa, pbase + row * 128 + ((c16 ^ (row & 7)) << 4));
            }
#pragma unroll
            for (int np = 0; np < 8; ++np) {
                uint32_t vb[4];
                int row = ks * 16 + rowoff;
                int c16 = 2 * np + kadd;
                ldm_x4t(vb, vst + row * 256 + ((c16 ^ (row & 7)) << 4));
                mma_f16(o[2 * np],     pa, vb[0], vb[1]);
                mma_f16(o[2 * np + 1], pa, vb[2], vb[3]);
            }
        }

        __syncthreads();
        if (t + 2 < 32) KV_FILL(t & 1, (t + 2) * 64);
        CP_COMMIT;
    }

    // ---- epilogue: normalize, store fp16 ----
    float li0 = 1.0f / l0, li1 = 1.0f / l1;
    __half* ObA = Og + (size_t)(b * S + q0 + w * 16 + g) * D + h * HD;
    __half* ObB = ObA + (size_t)8 * D;
#pragma unroll
    for (int nt = 0; nt < 16; ++nt) {
        int c = nt * 8 + 2 * tig;
        __half2 h0 = __floats2half2_rn(o[nt][0] * li0, o[nt][1] * li0);
        __half2 h1 = __floats2half2_rn(o[nt][2] * li1, o[nt][3] * li1);
        *(__half2*)(ObA + c) = h0;
        *(__half2*)(ObB + c) = h1;
    }
#undef KV_FILL
}

// ---------------------------------------------------------------------------
extern "C" void kernel_launch(void* const* d_in, const int* in_sizes, int n_in,
                              void* d_out, int out_size) {
    (void)in_sizes; (void)n_in; (void)out_size;
    const float* x        = (const float*)d_in[0];
    const int*   seq_lens = (const int*)  d_in[1];
    const float* freqs    = (const float*)d_in[2];
    const float* wq       = (const float*)d_in[3];
    const float* bq       = (const float*)d_in[4];
    const float* wk       = (const float*)d_in[5];
    const float* bk       = (const float*)d_in[6];
    const float* wv       = (const float*)d_in[7];
    const float* bv       = (const float*)d_in[8];
    const float* wo       = (const float*)d_in[9];
    const float* bo       = (const float*)d_in[10];
    const float* gq       = (const float*)d_in[11];
    const float* gk       = (const float*)d_in[12];
    float* out = (float*)d_out;

    __half *pxh, *pwh, *pq, *pk, *pv, *po;
    cudaGetSymbolAddress((void**)&pxh, g_xh);
    cudaGetSymbolAddress((void**)&pwh, g_wh);
    cudaGetSymbolAddress((void**)&pq, g_qh);
    cudaGetSymbolAddress((void**)&pk, g_kh);
    cudaGetSymbolAddress((void**)&pv, g_vh);
    cudaGetSymbolAddress((void**)&po, g_oh);
    __half* pw0 = pwh;
    __half* pw1 = pwh + (size_t)D * D;
    __half* pw2 = pwh + 2 * (size_t)D * D;
    __half* pw3 = pwh + 3 * (size_t)D * D;

    cudaFuncSetAttribute(gemm_f16, cudaFuncAttributeMaxDynamicSharedMemorySize,
                         GEMM_SMEM_BYTES);
    cudaFuncSetAttribute(flash_f16, cudaFuncAttributeMaxDynamicSharedMemorySize,
                         FA_SMEM_BYTES);

    conv_h<<<(M_ROWS * D / 4 + 255) / 256, 256>>>(x, pxh, M_ROWS * D / 4);
    conv_h<<<(D * D / 4 + 255) / 256, 256>>>(wq, pw0, D * D / 4);
    conv_h<<<(D * D / 4 + 255) / 256, 256>>>(wk, pw1, D * D / 4);
    conv_h<<<(D * D / 4 + 255) / 256, 256>>>(wv, pw2, D * D / 4);
    conv_h<<<(D * D / 4 + 255) / 256, 256>>>(wo, pw3, D * D / 4);

    dim3 ggrid(D / 256, M_ROWS / 128);  // (8, 32)
    gemm_f16<<<ggrid, 256, GEMM_SMEM_BYTES>>>(pxh, pw0, bq, pq, nullptr, 0);
    gemm_f16<<<ggrid, 256, GEMM_SMEM_BYTES>>>(pxh, pw1, bk, pk, nullptr, 0);
    gemm_f16<<<ggrid, 256, GEMM_SMEM_BYTES>>>(pxh, pw2, bv, pv, nullptr, 0);

    rmsnorm_rope_h<<<M_ROWS, 256>>>(pq, gq, freqs);
    rmsnorm_rope_h<<<M_ROWS, 256>>>(pk, gk, freqs);

    flash_f16<<<dim3(S / 128, B * NH), 256, FA_SMEM_BYTES>>>(
        pq, pk, pv, seq_lens, po);

    gemm_f16<<<ggrid, 256, GEMM_SMEM_BYTES>>>(po, pw3, bo, nullptr, out, 1);
}